// round 5
// baseline (speedup 1.0000x reference)
#include <cuda_runtime.h>
#include <cuda_bf16.h>
#include <cstdint>

#define NNODES 200000
#define NEDGES 600000
#define NCH    128
#define SK     136            // padded bf16 row stride
#define SKB    (SK * 2)
#define CHUNK  512
#define NCHUNK ((NNODES + CHUNK - 1) / CHUNK)   // 391

// ---------------- scratch ----------------
__device__ float g_h[(size_t)NNODES * NCH];
__device__ float g_acc[(size_t)NNODES * NCH];
__device__ float g_dinv[NNODES];
__device__ int   g_indeg[NNODES];
__device__ int   g_cursor[NNODES];
__device__ int   g_rowptr[NNODES];
__device__ int   g_bsum[CHUNK];
__device__ int   g_bbase[CHUNK];
__device__ int   g_esrc[NEDGES];
__device__ float g_sum[NCH];
__device__ float g_sumsq[NCH];
__device__ float g_scale[NCH];
__device__ float g_shift[NCH];
__device__ __nv_bfloat16 g_Wt[4][NCH * NCH];   // W1hi W1lo W2hi W2lo, [n][k]

// ---------------- prep ----------------
// transpose + split weights; also zero BN accumulators (runs first)
__global__ void k_convW(const float* __restrict__ W1, const float* __restrict__ W2) {
    int idx = blockIdx.x * blockDim.x + threadIdx.x;
    if (idx < NCH) { g_sum[idx] = 0.f; g_sumsq[idx] = 0.f; }
    if (idx >= NCH * NCH) return;
    int nn = idx & 127, kk = idx >> 7;
    int o = nn * NCH + kk;
    float v1 = W1[idx], v2 = W2[idx];
    __nv_bfloat16 h1 = __float2bfloat16(v1);
    __nv_bfloat16 h2 = __float2bfloat16(v2);
    g_Wt[0][o] = h1; g_Wt[1][o] = __float2bfloat16(v1 - __bfloat162float(h1));
    g_Wt[2][o] = h2; g_Wt[3][o] = __float2bfloat16(v2 - __bfloat162float(h2));
}

// channel stats of PReLU(x): 4 independent row streams per thread
__global__ void k_stats(const float* __restrict__ x, const float* __restrict__ aP, int n) {
    __shared__ float4 rs[8][32];
    __shared__ float4 rq[8][32];
    int tid = threadIdx.x, c4 = tid & 31, ry = tid >> 5;
    float av = aP[0];
    float4 s = make_float4(0, 0, 0, 0), q = make_float4(0, 0, 0, 0);
    for (int base = blockIdx.x * 32; base < n; base += gridDim.x * 32) {
#pragma unroll
        for (int u = 0; u < 4; u++) {
            int r = base + ry + u * 8;
            if (r < n) {
                float4 v = ((const float4*)x)[(size_t)r * 32 + c4];
                v.x = v.x >= 0.f ? v.x : av * v.x;
                v.y = v.y >= 0.f ? v.y : av * v.y;
                v.z = v.z >= 0.f ? v.z : av * v.z;
                v.w = v.w >= 0.f ? v.w : av * v.w;
                s.x += v.x; s.y += v.y; s.z += v.z; s.w += v.w;
                q.x += v.x * v.x; q.y += v.y * v.y; q.z += v.z * v.z; q.w += v.w * v.w;
            }
        }
    }
    rs[ry][c4] = s; rq[ry][c4] = q;
    __syncthreads();
    if (ry == 0) {
        float4 S = rs[0][c4], Q = rq[0][c4];
#pragma unroll
        for (int i = 1; i < 8; i++) {
            float4 a = rs[i][c4], b = rq[i][c4];
            S.x += a.x; S.y += a.y; S.z += a.z; S.w += a.w;
            Q.x += b.x; Q.y += b.y; Q.z += b.z; Q.w += b.w;
        }
        atomicAdd(&g_sum[c4 * 4 + 0], S.x); atomicAdd(&g_sum[c4 * 4 + 1], S.y);
        atomicAdd(&g_sum[c4 * 4 + 2], S.z); atomicAdd(&g_sum[c4 * 4 + 3], S.w);
        atomicAdd(&g_sumsq[c4 * 4 + 0], Q.x); atomicAdd(&g_sumsq[c4 * 4 + 1], Q.y);
        atomicAdd(&g_sumsq[c4 * 4 + 2], Q.z); atomicAdd(&g_sumsq[c4 * 4 + 3], Q.w);
    }
}

__global__ void k_finalize(const float* __restrict__ gamma, const float* __restrict__ beta, int n) {
    int c = threadIdx.x;
    if (c >= NCH) return;
    float invn = 1.0f / (float)n;
    float mean = g_sum[c] * invn;
    float var  = g_sumsq[c] * invn - mean * mean;
    float sc   = gamma[c] * rsqrtf(var + 1e-5f);
    g_scale[c] = sc;
    g_shift[c] = beta[c] - mean * sc;
}

__global__ void k_zero(int n) {
    int i = blockIdx.x * blockDim.x + threadIdx.x;
    if (i < n) { g_indeg[i] = 0; g_cursor[i] = 0; }
}
__global__ void k_count(const int* __restrict__ dst, int e) {
    int i = blockIdx.x * blockDim.x + threadIdx.x;
    if (i < e) atomicAdd(&g_indeg[dst[i]], 1);
}
__global__ void k_dinv(int n) {
    int i = blockIdx.x * blockDim.x + threadIdx.x;
    if (i < n) g_dinv[i] = rsqrtf((float)(g_indeg[i] + 1));
}

// ---- block scan ----
__global__ void k_scan1(int n) {
    __shared__ int sh[CHUNK];
    int i = blockIdx.x * CHUNK + threadIdx.x;
    sh[threadIdx.x] = (i < n) ? g_indeg[i] : 0;
    __syncthreads();
    for (int s = CHUNK / 2; s > 0; s >>= 1) {
        if (threadIdx.x < s) sh[threadIdx.x] += sh[threadIdx.x + s];
        __syncthreads();
    }
    if (threadIdx.x == 0) g_bsum[blockIdx.x] = sh[0];
}
__global__ void k_scan2() {
    __shared__ int sh[CHUNK];
    int t = threadIdx.x;
    sh[t] = (t < NCHUNK) ? g_bsum[t] : 0;
    __syncthreads();
    for (int d = 1; d < CHUNK; d <<= 1) {
        int v = (t >= d) ? sh[t - d] : 0;
        __syncthreads();
        sh[t] += v;
        __syncthreads();
    }
    if (t < NCHUNK) g_bbase[t] = (t == 0) ? 0 : sh[t - 1];
}
__global__ void k_scan3(int n) {
    __shared__ int sh[CHUNK];
    int t = threadIdx.x;
    int i = blockIdx.x * CHUNK + t;
    int v0 = (i < n) ? g_indeg[i] : 0;
    sh[t] = v0;
    __syncthreads();
    for (int d = 1; d < CHUNK; d <<= 1) {
        int v = (t >= d) ? sh[t - d] : 0;
        __syncthreads();
        sh[t] += v;
        __syncthreads();
    }
    if (i < n) g_rowptr[i] = g_bbase[blockIdx.x] + sh[t] - v0;
}
__global__ void k_fill(const int* __restrict__ src, const int* __restrict__ dst, int e) {
    int i = blockIdx.x * blockDim.x + threadIdx.x;
    if (i >= e) return;
    int d = dst[i];
    int pos = g_rowptr[d] + atomicAdd(&g_cursor[d], 1);
    g_esrc[pos] = src[i];
}

// ---------------- HMMA helpers ----------------
__device__ __forceinline__ void mma16816(float* c, const uint32_t* a, const uint32_t* b) {
    asm volatile(
        "mma.sync.aligned.m16n8k16.row.col.f32.bf16.bf16.f32 "
        "{%0,%1,%2,%3}, {%4,%5,%6,%7}, {%8,%9}, {%0,%1,%2,%3};"
        : "+f"(c[0]), "+f"(c[1]), "+f"(c[2]), "+f"(c[3])
        : "r"(a[0]), "r"(a[1]), "r"(a[2]), "r"(a[3]), "r"(b[0]), "r"(b[1]));
}
__device__ __forceinline__ uint32_t lds32(const char* p) { return *(const uint32_t*)p; }
__device__ __forceinline__ uint32_t pack_bf2(float x, float y) {
    __nv_bfloat162 h = __floats2bfloat162_rn(x, y);
    return *(uint32_t*)&h;
}

// ---------------- GEMM: g_h = f(A) @ W ----------------
template <int MODE>
__global__ void __launch_bounds__(256)
k_mma(const float* __restrict__ Ain,
      const __nv_bfloat16* __restrict__ Whi, const __nv_bfloat16* __restrict__ Wlo,
      const float* __restrict__ aP, int n)
{
    extern __shared__ char sm[];
    const int AH = 0, AL = 128 * SKB, WH = 2 * 128 * SKB, WL = 3 * 128 * SKB;
    int tid = threadIdx.x;
    float av = aP[0];
    int row0 = blockIdx.x * 128;

    {
        int rl = tid >> 1, half = tid & 1;
        int r = row0 + rl;
        char* dh = sm + AH + rl * SKB + half * 128;
        char* dl = sm + AL + rl * SKB + half * 128;
        if (r < n) {
            const float4* A4 = (const float4*)(Ain + (size_t)r * NCH) + half * 16;
#pragma unroll
            for (int q = 0; q < 16; q++) {
                float4 v = A4[q];
                v.x = v.x >= 0.f ? v.x : av * v.x;
                v.y = v.y >= 0.f ? v.y : av * v.y;
                v.z = v.z >= 0.f ? v.z : av * v.z;
                v.w = v.w >= 0.f ? v.w : av * v.w;
                if (MODE == 0) {
                    float4 sc = ((const float4*)g_scale)[half * 16 + q];
                    float4 sf = ((const float4*)g_shift)[half * 16 + q];
                    v.x = fmaf(v.x, sc.x, sf.x); v.y = fmaf(v.y, sc.y, sf.y);
                    v.z = fmaf(v.z, sc.z, sf.z); v.w = fmaf(v.w, sc.w, sf.w);
                }
                __nv_bfloat16 hx = __float2bfloat16(v.x), hy = __float2bfloat16(v.y);
                __nv_bfloat16 hz = __float2bfloat16(v.z), hw = __float2bfloat16(v.w);
                uint2 hi; hi.x = pack_bf2(v.x, v.y); hi.y = pack_bf2(v.z, v.w);
                float lx = v.x - __bfloat162float(hx), ly = v.y - __bfloat162float(hy);
                float lz = v.z - __bfloat162float(hz), lw = v.w - __bfloat162float(hw);
                uint2 lo; lo.x = pack_bf2(lx, ly); lo.y = pack_bf2(lz, lw);
                *(uint2*)(dh + q * 8) = hi;
                *(uint2*)(dl + q * 8) = lo;
            }
        } else {
#pragma unroll
            for (int q = 0; q < 16; q++) {
                *(uint2*)(dh + q * 8) = make_uint2(0, 0);
                *(uint2*)(dl + q * 8) = make_uint2(0, 0);
            }
        }
    }
    {
        const uint4* wh4 = (const uint4*)Whi;
        const uint4* wl4 = (const uint4*)Wlo;
#pragma unroll
        for (int i = 0; i < 8; i++) {
            int idx = tid + i * 256;
            int rw = idx >> 4, cm = idx & 15;
            *(uint4*)(sm + WH + rw * SKB + cm * 16) = wh4[idx];
            *(uint4*)(sm + WL + rw * SKB + cm * 16) = wl4[idx];
        }
    }
    __syncthreads();

    int warp = tid >> 5, lane = tid & 31;
    int g = lane >> 2, tg = lane & 3;
    int m0 = (warp & 3) * 32;
    int n0 = (warp >> 2) * 64;

    float acc[2][8][4];
#pragma unroll
    for (int mt = 0; mt < 2; mt++)
#pragma unroll
        for (int j = 0; j < 8; j++)
#pragma unroll
            for (int v = 0; v < 4; v++) acc[mt][j][v] = 0.f;

#pragma unroll
    for (int kc = 0; kc < 8; kc++) {
        int k0 = kc * 16;
        uint32_t ah[2][4], al[2][4];
#pragma unroll
        for (int mt = 0; mt < 2; mt++) {
            int ar = m0 + mt * 16 + g;
            const char* ph = sm + AH + ar * SKB + (k0 + 2 * tg) * 2;
            const char* pl = sm + AL + ar * SKB + (k0 + 2 * tg) * 2;
            ah[mt][0] = lds32(ph);                al[mt][0] = lds32(pl);
            ah[mt][1] = lds32(ph + 8 * SKB);      al[mt][1] = lds32(pl + 8 * SKB);
            ah[mt][2] = lds32(ph + 16);           al[mt][2] = lds32(pl + 16);
            ah[mt][3] = lds32(ph + 8 * SKB + 16); al[mt][3] = lds32(pl + 8 * SKB + 16);
        }
#pragma unroll
        for (int j = 0; j < 8; j++) {
            int br = n0 + j * 8 + g;
            const char* qh = sm + WH + br * SKB + (k0 + 2 * tg) * 2;
            const char* ql = sm + WL + br * SKB + (k0 + 2 * tg) * 2;
            uint32_t bh[2], bl[2];
            bh[0] = lds32(qh); bh[1] = lds32(qh + 16);
            bl[0] = lds32(ql); bl[1] = lds32(ql + 16);
#pragma unroll
            for (int mt = 0; mt < 2; mt++) {
                mma16816(acc[mt][j], ah[mt], bh);
                mma16816(acc[mt][j], ah[mt], bl);
                mma16816(acc[mt][j], al[mt], bh);
            }
        }
    }

#pragma unroll
    for (int mt = 0; mt < 2; mt++) {
        int rA = row0 + m0 + mt * 16 + g;
        int rB = rA + 8;
#pragma unroll
        for (int j = 0; j < 8; j++) {
            int col = n0 + j * 8 + 2 * tg;
            if (rA < n)
                *(float2*)(g_h + (size_t)rA * NCH + col) = make_float2(acc[mt][j][0], acc[mt][j][1]);
            if (rB < n)
                *(float2*)(g_h + (size_t)rB * NCH + col) = make_float2(acc[mt][j][2], acc[mt][j][3]);
        }
    }
}

// ---------------- CSR gather, high-MLP ----------------
// out[d] = h[d]/deg + b + sum_{s in N(d)} dinv[s]*dinv[d]*h[s]
__global__ void k_gather(const float* __restrict__ bvec, float* __restrict__ out, int n) {
    int warp = (blockIdx.x * blockDim.x + threadIdx.x) >> 5;
    int lane = threadIdx.x & 31;
    if (warp >= n) return;
    int off = g_rowptr[warp];
    int cnt = g_indeg[warp];
    float dr = g_dinv[warp];
    float inv = dr * dr;
    float4 hv = __ldg(((const float4*)(g_h + (size_t)warp * NCH)) + lane);
    float4 bb = __ldg(((const float4*)bvec) + lane);
    float4 acc = make_float4(fmaf(hv.x, inv, bb.x), fmaf(hv.y, inv, bb.y),
                             fmaf(hv.z, inv, bb.z), fmaf(hv.w, inv, bb.w));
    for (int base = 0; base < cnt; base += 32) {
        int m = cnt - base; if (m > 32) m = 32;
        // lane-parallel index + coefficient fetch (coalesced esrc, 1 gather for dinv)
        int   sidx = 0;
        float scoef = 0.f;
        if (lane < m) {
            sidx  = __ldg(g_esrc + off + base + lane);
            scoef = __ldg(g_dinv + sidx) * dr;
        }
        int j = 0;
#pragma unroll 1
        for (; j + 4 <= m; j += 4) {
            int s0 = __shfl_sync(0xffffffffu, sidx, j);
            int s1 = __shfl_sync(0xffffffffu, sidx, j + 1);
            int s2 = __shfl_sync(0xffffffffu, sidx, j + 2);
            int s3 = __shfl_sync(0xffffffffu, sidx, j + 3);
            float c0 = __shfl_sync(0xffffffffu, scoef, j);
            float c1 = __shfl_sync(0xffffffffu, scoef, j + 1);
            float c2 = __shfl_sync(0xffffffffu, scoef, j + 2);
            float c3 = __shfl_sync(0xffffffffu, scoef, j + 3);
            float4 v0 = __ldg(((const float4*)(g_h + (size_t)s0 * NCH)) + lane);
            float4 v1 = __ldg(((const float4*)(g_h + (size_t)s1 * NCH)) + lane);
            float4 v2 = __ldg(((const float4*)(g_h + (size_t)s2 * NCH)) + lane);
            float4 v3 = __ldg(((const float4*)(g_h + (size_t)s3 * NCH)) + lane);
            acc.x = fmaf(v0.x, c0, acc.x); acc.y = fmaf(v0.y, c0, acc.y);
            acc.z = fmaf(v0.z, c0, acc.z); acc.w = fmaf(v0.w, c0, acc.w);
            acc.x = fmaf(v1.x, c1, acc.x); acc.y = fmaf(v1.y, c1, acc.y);
            acc.z = fmaf(v1.z, c1, acc.z); acc.w = fmaf(v1.w, c1, acc.w);
            acc.x = fmaf(v2.x, c2, acc.x); acc.y = fmaf(v2.y, c2, acc.y);
            acc.z = fmaf(v2.z, c2, acc.z); acc.w = fmaf(v2.w, c2, acc.w);
            acc.x = fmaf(v3.x, c3, acc.x); acc.y = fmaf(v3.y, c3, acc.y);
            acc.z = fmaf(v3.z, c3, acc.z); acc.w = fmaf(v3.w, c3, acc.w);
        }
        for (; j < m; j++) {
            int s0 = __shfl_sync(0xffffffffu, sidx, j);
            float c0 = __shfl_sync(0xffffffffu, scoef, j);
            float4 v0 = __ldg(((const float4*)(g_h + (size_t)s0 * NCH)) + lane);
            acc.x = fmaf(v0.x, c0, acc.x); acc.y = fmaf(v0.y, c0, acc.y);
            acc.z = fmaf(v0.z, c0, acc.z); acc.w = fmaf(v0.w, c0, acc.w);
        }
    }
    ((float4*)(out + (size_t)warp * NCH))[lane] = acc;
}

// ---------------- launch ----------------
extern "C" void kernel_launch(void* const* d_in, const int* in_sizes, int n_in,
                              void* d_out, int out_size) {
    const float* x     = (const float*)d_in[0];
    const int*   ei    = (const int*)  d_in[1];
    const float* a1    = (const float*)d_in[2];
    const float* gamma = (const float*)d_in[3];
    const float* beta  = (const float*)d_in[4];
    const float* W1    = (const float*)d_in[5];
    const float* b1    = (const float*)d_in[6];
    const float* a2    = (const float*)d_in[7];
    const float* W2    = (const float*)d_in[8];
    const float* b2    = (const float*)d_in[9];
    float* out = (float*)d_out;

    int n = in_sizes[0] / NCH;
    int e = in_sizes[1] / 2;
    const int* src = ei;
    const int* dst = ei + e;

    const int SMEM = 4 * 128 * SKB;
    cudaFuncSetAttribute(k_mma<0>, cudaFuncAttributeMaxDynamicSharedMemorySize, SMEM);
    cudaFuncSetAttribute(k_mma<1>, cudaFuncAttributeMaxDynamicSharedMemorySize, SMEM);

    float* accPtr = nullptr;
    cudaGetSymbolAddress((void**)&accPtr, g_acc);
    __nv_bfloat16* wtPtr = nullptr;
    cudaGetSymbolAddress((void**)&wtPtr, g_Wt);

    int mmaBlocks = (n + 127) / 128;
    int gatBlocks = (int)(((long long)n * 32 + 255) / 256);

    // 1-3: BN stats path (convW also zeroes accumulators)
    k_convW<<<(NCH * NCH + 255) / 256, 256>>>(W1, W2);
    k_stats<<<1184, 256>>>(x, a1, n);
    k_finalize<<<1, 128>>>(gamma, beta, n);
    // 4: conv1 GEMM  (lands in the ncu profile slot)
    k_mma<0><<<mmaBlocks, 256, SMEM>>>(x, wtPtr + 0 * NCH * NCH, wtPtr + 1 * NCH * NCH, a1, n);
    // CSR build (overlaps nothing, but order-independent of mma<0>)
    k_zero<<<(n + 255) / 256, 256>>>(n);
    k_count<<<(e + 255) / 256, 256>>>(dst, e);
    k_scan1<<<NCHUNK, CHUNK>>>(n);
    k_scan2<<<1, CHUNK>>>();
    k_scan3<<<NCHUNK, CHUNK>>>(n);
    k_dinv<<<(n + 255) / 256, 256>>>(n);
    k_fill<<<(e + 255) / 256, 256>>>(src, dst, e);
    // conv1 aggregate
    k_gather<<<gatBlocks, 256>>>(b1, accPtr, n);
    // conv2
    k_mma<1><<<mmaBlocks, 256, SMEM>>>(accPtr, wtPtr + 2 * NCH * NCH, wtPtr + 3 * NCH * NCH, a2, n);
    k_gather<<<gatBlocks, 256>>>(b2, out, n);
}

// round 9
// speedup vs baseline: 1.1365x; 1.1365x over previous
#include <cuda_runtime.h>
#include <cuda_bf16.h>
#include <cstdint>

#define NNODES 200000
#define NEDGES 600000
#define NCH    128
#define SK     136            // padded bf16 row stride
#define SKB    (SK * 2)
#define CHUNK  512
#define NCHUNK ((NNODES + CHUNK - 1) / CHUNK)   // 391

// ---------------- scratch ----------------
__device__ float g_h[(size_t)NNODES * NCH];
__device__ float g_acc[(size_t)NNODES * NCH];
__device__ float g_dinv[NNODES];
__device__ int   g_indeg[NNODES];
__device__ int   g_cursor[NNODES];
__device__ int   g_rowptr[NNODES];
__device__ int   g_bsum[CHUNK];
__device__ int   g_bbase[CHUNK];
__device__ int   g_esrc[NEDGES];
__device__ float g_sum[NCH];
__device__ float g_sumsq[NCH];
__device__ float g_scale[NCH];
__device__ float g_shift[NCH];
__device__ __nv_bfloat16 g_Wt[4][NCH * NCH];   // W1hi W1lo W2hi W2lo, [n][k]

// ---------------- prep ----------------
__global__ void k_convW(const float* __restrict__ W1, const float* __restrict__ W2) {
    int idx = blockIdx.x * blockDim.x + threadIdx.x;
    if (idx < NCH) { g_sum[idx] = 0.f; g_sumsq[idx] = 0.f; }
    if (idx >= NCH * NCH) return;
    int nn = idx & 127, kk = idx >> 7;
    int o = nn * NCH + kk;
    float v1 = W1[idx], v2 = W2[idx];
    __nv_bfloat16 h1 = __float2bfloat16(v1);
    __nv_bfloat16 h2 = __float2bfloat16(v2);
    g_Wt[0][o] = h1; g_Wt[1][o] = __float2bfloat16(v1 - __bfloat162float(h1));
    g_Wt[2][o] = h2; g_Wt[3][o] = __float2bfloat16(v2 - __bfloat162float(h2));
}

__global__ void k_stats(const float* __restrict__ x, const float* __restrict__ aP, int n) {
    __shared__ float4 rs[8][32];
    __shared__ float4 rq[8][32];
    int tid = threadIdx.x, c4 = tid & 31, ry = tid >> 5;
    float av = aP[0];
    float4 s = make_float4(0, 0, 0, 0), q = make_float4(0, 0, 0, 0);
    for (int base = blockIdx.x * 32; base < n; base += gridDim.x * 32) {
#pragma unroll
        for (int u = 0; u < 4; u++) {
            int r = base + ry + u * 8;
            if (r < n) {
                float4 v = ((const float4*)x)[(size_t)r * 32 + c4];
                v.x = v.x >= 0.f ? v.x : av * v.x;
                v.y = v.y >= 0.f ? v.y : av * v.y;
                v.z = v.z >= 0.f ? v.z : av * v.z;
                v.w = v.w >= 0.f ? v.w : av * v.w;
                s.x += v.x; s.y += v.y; s.z += v.z; s.w += v.w;
                q.x += v.x * v.x; q.y += v.y * v.y; q.z += v.z * v.z; q.w += v.w * v.w;
            }
        }
    }
    rs[ry][c4] = s; rq[ry][c4] = q;
    __syncthreads();
    if (ry == 0) {
        float4 S = rs[0][c4], Q = rq[0][c4];
#pragma unroll
        for (int i = 1; i < 8; i++) {
            float4 a = rs[i][c4], b = rq[i][c4];
            S.x += a.x; S.y += a.y; S.z += a.z; S.w += a.w;
            Q.x += b.x; Q.y += b.y; Q.z += b.z; Q.w += b.w;
        }
        atomicAdd(&g_sum[c4 * 4 + 0], S.x); atomicAdd(&g_sum[c4 * 4 + 1], S.y);
        atomicAdd(&g_sum[c4 * 4 + 2], S.z); atomicAdd(&g_sum[c4 * 4 + 3], S.w);
        atomicAdd(&g_sumsq[c4 * 4 + 0], Q.x); atomicAdd(&g_sumsq[c4 * 4 + 1], Q.y);
        atomicAdd(&g_sumsq[c4 * 4 + 2], Q.z); atomicAdd(&g_sumsq[c4 * 4 + 3], Q.w);
    }
}

__global__ void k_finalize(const float* __restrict__ gamma, const float* __restrict__ beta, int n) {
    int c = threadIdx.x;
    if (c >= NCH) return;
    float invn = 1.0f / (float)n;
    float mean = g_sum[c] * invn;
    float var  = g_sumsq[c] * invn - mean * mean;
    float sc   = gamma[c] * rsqrtf(var + 1e-5f);
    g_scale[c] = sc;
    g_shift[c] = beta[c] - mean * sc;
}

__global__ void k_zero(int n) {
    int i = blockIdx.x * blockDim.x + threadIdx.x;
    if (i < n) { g_indeg[i] = 0; g_cursor[i] = 0; }
}
__global__ void k_count(const int* __restrict__ dst, int e) {
    int i = blockIdx.x * blockDim.x + threadIdx.x;
    if (i < e) atomicAdd(&g_indeg[dst[i]], 1);
}
__global__ void k_dinv(int n) {
    int i = blockIdx.x * blockDim.x + threadIdx.x;
    if (i < n) g_dinv[i] = rsqrtf((float)(g_indeg[i] + 1));
}

__global__ void k_scan1(int n) {
    __shared__ int sh[CHUNK];
    int i = blockIdx.x * CHUNK + threadIdx.x;
    sh[threadIdx.x] = (i < n) ? g_indeg[i] : 0;
    __syncthreads();
    for (int s = CHUNK / 2; s > 0; s >>= 1) {
        if (threadIdx.x < s) sh[threadIdx.x] += sh[threadIdx.x + s];
        __syncthreads();
    }
    if (threadIdx.x == 0) g_bsum[blockIdx.x] = sh[0];
}
__global__ void k_scan2() {
    __shared__ int sh[CHUNK];
    int t = threadIdx.x;
    sh[t] = (t < NCHUNK) ? g_bsum[t] : 0;
    __syncthreads();
    for (int d = 1; d < CHUNK; d <<= 1) {
        int v = (t >= d) ? sh[t - d] : 0;
        __syncthreads();
        sh[t] += v;
        __syncthreads();
    }
    if (t < NCHUNK) g_bbase[t] = (t == 0) ? 0 : sh[t - 1];
}
__global__ void k_scan3(int n) {
    __shared__ int sh[CHUNK];
    int t = threadIdx.x;
    int i = blockIdx.x * CHUNK + t;
    int v0 = (i < n) ? g_indeg[i] : 0;
    sh[t] = v0;
    __syncthreads();
    for (int d = 1; d < CHUNK; d <<= 1) {
        int v = (t >= d) ? sh[t - d] : 0;
        __syncthreads();
        sh[t] += v;
        __syncthreads();
    }
    if (i < n) g_rowptr[i] = g_bbase[blockIdx.x] + sh[t] - v0;
}
__global__ void k_fill(const int* __restrict__ src, const int* __restrict__ dst, int e) {
    int i = blockIdx.x * blockDim.x + threadIdx.x;
    if (i >= e) return;
    int d = dst[i];
    int pos = g_rowptr[d] + atomicAdd(&g_cursor[d], 1);
    g_esrc[pos] = src[i];
}

// ---------------- HMMA helpers ----------------
__device__ __forceinline__ void mma16816(float* c, const uint32_t* a, const uint32_t* b) {
    asm volatile(
        "mma.sync.aligned.m16n8k16.row.col.f32.bf16.bf16.f32 "
        "{%0,%1,%2,%3}, {%4,%5,%6,%7}, {%8,%9}, {%0,%1,%2,%3};"
        : "+f"(c[0]), "+f"(c[1]), "+f"(c[2]), "+f"(c[3])
        : "r"(a[0]), "r"(a[1]), "r"(a[2]), "r"(a[3]), "r"(b[0]), "r"(b[1]));
}
__device__ __forceinline__ void ldsm4(uint32_t* r, uint32_t addr) {
    asm volatile("ldmatrix.sync.aligned.m8n8.x4.shared.b16 {%0,%1,%2,%3}, [%4];"
                 : "=r"(r[0]), "=r"(r[1]), "=r"(r[2]), "=r"(r[3]) : "r"(addr));
}
__device__ __forceinline__ uint32_t pack_bf2(float x, float y) {
    __nv_bfloat162 h = __floats2bfloat162_rn(x, y);
    return *(uint32_t*)&h;
}

// ---------------- GEMM: g_h = f(A) @ W  (ldmatrix fragment loads) ----------------
template <int MODE>
__global__ void __launch_bounds__(256)
k_mma(const float* __restrict__ Ain,
      const __nv_bfloat16* __restrict__ Whi, const __nv_bfloat16* __restrict__ Wlo,
      const float* __restrict__ aP, int n)
{
    extern __shared__ char sm[];
    const int AH = 0, AL = 128 * SKB, WH = 2 * 128 * SKB, WL = 3 * 128 * SKB;
    int tid = threadIdx.x;
    float av = aP[0];
    int row0 = blockIdx.x * 128;

    // ---- A tile: load, transform, hi/lo split ----
    {
        int rl = tid >> 1, half = tid & 1;
        int r = row0 + rl;
        char* dh = sm + AH + rl * SKB + half * 128;
        char* dl = sm + AL + rl * SKB + half * 128;
        if (r < n) {
            const float4* A4 = (const float4*)(Ain + (size_t)r * NCH) + half * 16;
#pragma unroll
            for (int q = 0; q < 16; q++) {
                float4 v = A4[q];
                v.x = v.x >= 0.f ? v.x : av * v.x;
                v.y = v.y >= 0.f ? v.y : av * v.y;
                v.z = v.z >= 0.f ? v.z : av * v.z;
                v.w = v.w >= 0.f ? v.w : av * v.w;
                if (MODE == 0) {
                    float4 sc = ((const float4*)g_scale)[half * 16 + q];
                    float4 sf = ((const float4*)g_shift)[half * 16 + q];
                    v.x = fmaf(v.x, sc.x, sf.x); v.y = fmaf(v.y, sc.y, sf.y);
                    v.z = fmaf(v.z, sc.z, sf.z); v.w = fmaf(v.w, sc.w, sf.w);
                }
                __nv_bfloat16 hx = __float2bfloat16(v.x), hy = __float2bfloat16(v.y);
                __nv_bfloat16 hz = __float2bfloat16(v.z), hw = __float2bfloat16(v.w);
                uint2 hi; hi.x = pack_bf2(v.x, v.y); hi.y = pack_bf2(v.z, v.w);
                float lx = v.x - __bfloat162float(hx), ly = v.y - __bfloat162float(hy);
                float lz = v.z - __bfloat162float(hz), lw = v.w - __bfloat162float(hw);
                uint2 lo; lo.x = pack_bf2(lx, ly); lo.y = pack_bf2(lz, lw);
                *(uint2*)(dh + q * 8) = hi;
                *(uint2*)(dl + q * 8) = lo;
            }
        } else {
#pragma unroll
            for (int q = 0; q < 16; q++) {
                *(uint2*)(dh + q * 8) = make_uint2(0, 0);
                *(uint2*)(dl + q * 8) = make_uint2(0, 0);
            }
        }
    }
    // ---- W splits ----
    {
        const uint4* wh4 = (const uint4*)Whi;
        const uint4* wl4 = (const uint4*)Wlo;
#pragma unroll
        for (int i = 0; i < 8; i++) {
            int idx = tid + i * 256;
            int rw = idx >> 4, cm = idx & 15;
            *(uint4*)(sm + WH + rw * SKB + cm * 16) = wh4[idx];
            *(uint4*)(sm + WL + rw * SKB + cm * 16) = wl4[idx];
        }
    }
    __syncthreads();

    int warp = tid >> 5, lane = tid & 31;
    int g = lane >> 2, tg = lane & 3;
    int m0 = (warp & 3) * 32;
    int n0 = (warp >> 2) * 64;
    int sel = lane >> 3, rowin = lane & 7;

    uint32_t sbase = (uint32_t)__cvta_generic_to_shared(sm);
    // A ldmatrix lane addresses: regs {a0,a1,a2,a3} <- mats {rows0-7/k0, rows8-15/k0, rows0-7/k8, rows8-15/k8}
    // lane L: mat = L>>3 -> ar = m0+mt*16 + (sel&1)*8 + rowin ; kbyte = (sel>>1)*16
    uint32_t aoffA = (uint32_t)((m0 + (sel & 1) * 8 + rowin) * SKB + (sel >> 1) * 16);
    // B: regs {b0_j,b1_j,b0_j+1,b1_j+1} <- mats {n0-7/k0, n0-7/k8, n8-15/k0, n8-15/k8}
    // lane L: nr = n0+jp*16 + (sel>>1)*8 + rowin ; kbyte = (sel&1)*16
    uint32_t boffB = (uint32_t)((n0 + (sel >> 1) * 8 + rowin) * SKB + (sel & 1) * 16);

    float acc[2][8][4];
#pragma unroll
    for (int mt = 0; mt < 2; mt++)
#pragma unroll
        for (int j = 0; j < 8; j++)
#pragma unroll
            for (int v = 0; v < 4; v++) acc[mt][j][v] = 0.f;

#pragma unroll
    for (int kc = 0; kc < 8; kc++) {
        uint32_t kb = kc * 32;   // 16 bf16 = 32 bytes
        uint32_t ah[2][4], al[2][4];
#pragma unroll
        for (int mt = 0; mt < 2; mt++) {
            ldsm4(ah[mt], sbase + AH + aoffA + mt * (16 * SKB) + kb);
            ldsm4(al[mt], sbase + AL + aoffA + mt * (16 * SKB) + kb);
        }
#pragma unroll
        for (int jp = 0; jp < 4; jp++) {
            uint32_t bh[4], bl[4];
            ldsm4(bh, sbase + WH + boffB + jp * (16 * SKB) + kb);
            ldsm4(bl, sbase + WL + boffB + jp * (16 * SKB) + kb);
#pragma unroll
            for (int half = 0; half < 2; half++) {
                int j = jp * 2 + half;
#pragma unroll
                for (int mt = 0; mt < 2; mt++) {
                    mma16816(acc[mt][j], ah[mt], bh + half * 2);
                    mma16816(acc[mt][j], ah[mt], bl + half * 2);
                    mma16816(acc[mt][j], al[mt], bh + half * 2);
                }
            }
        }
    }

#pragma unroll
    for (int mt = 0; mt < 2; mt++) {
        int rA = row0 + m0 + mt * 16 + g;
        int rB = rA + 8;
#pragma unroll
        for (int j = 0; j < 8; j++) {
            int col = n0 + j * 8 + 2 * tg;
            if (rA < n)
                *(float2*)(g_h + (size_t)rA * NCH + col) = make_float2(acc[mt][j][0], acc[mt][j][1]);
            if (rB < n)
                *(float2*)(g_h + (size_t)rB * NCH + col) = make_float2(acc[mt][j][2], acc[mt][j][3]);
        }
    }
}

// ---------------- CSR gather (R4 form — simple broadcast loop) ----------------
__global__ void k_gather(const float* __restrict__ bvec, float* __restrict__ out, int n) {
    int warp = (blockIdx.x * blockDim.x + threadIdx.x) >> 5;
    int lane = threadIdx.x & 31;
    if (warp >= n) return;
    int off = g_rowptr[warp];
    int cnt = g_indeg[warp];
    float dr = g_dinv[warp];
    float inv = dr * dr;
    float4 hv = ((const float4*)(g_h + (size_t)warp * NCH))[lane];
    float4 bb = ((const float4*)bvec)[lane];
    float4 acc = make_float4(fmaf(hv.x, inv, bb.x), fmaf(hv.y, inv, bb.y),
                             fmaf(hv.z, inv, bb.z), fmaf(hv.w, inv, bb.w));
    for (int j = 0; j < cnt; j++) {
        int s = g_esrc[off + j];
        float c = g_dinv[s] * dr;
        float4 sv = ((const float4*)(g_h + (size_t)s * NCH))[lane];
        acc.x = fmaf(sv.x, c, acc.x);
        acc.y = fmaf(sv.y, c, acc.y);
        acc.z = fmaf(sv.z, c, acc.z);
        acc.w = fmaf(sv.w, c, acc.w);
    }
    ((float4*)(out + (size_t)warp * NCH))[lane] = acc;
}

// ---------------- launch ----------------
extern "C" void kernel_launch(void* const* d_in, const int* in_sizes, int n_in,
                              void* d_out, int out_size) {
    const float* x     = (const float*)d_in[0];
    const int*   ei    = (const int*)  d_in[1];
    const float* a1    = (const float*)d_in[2];
    const float* gamma = (const float*)d_in[3];
    const float* beta  = (const float*)d_in[4];
    const float* W1    = (const float*)d_in[5];
    const float* b1    = (const float*)d_in[6];
    const float* a2    = (const float*)d_in[7];
    const float* W2    = (const float*)d_in[8];
    const float* b2    = (const float*)d_in[9];
    float* out = (float*)d_out;

    int n = in_sizes[0] / NCH;
    int e = in_sizes[1] / 2;
    const int* src = ei;
    const int* dst = ei + e;

    const int SMEM = 4 * 128 * SKB;
    cudaFuncSetAttribute(k_mma<0>, cudaFuncAttributeMaxDynamicSharedMemorySize, SMEM);
    cudaFuncSetAttribute(k_mma<1>, cudaFuncAttributeMaxDynamicSharedMemorySize, SMEM);

    float* accPtr = nullptr;
    cudaGetSymbolAddress((void**)&accPtr, g_acc);
    __nv_bfloat16* wtPtr = nullptr;
    cudaGetSymbolAddress((void**)&wtPtr, g_Wt);

    int mmaBlocks = (n + 127) / 128;
    int gatBlocks = (int)(((long long)n * 32 + 255) / 256);

    // 1-3: BN stats path
    k_convW<<<(NCH * NCH + 255) / 256, 256>>>(W1, W2);
    k_stats<<<1184, 256>>>(x, a1, n);
    k_finalize<<<1, 128>>>(gamma, beta, n);
    // 4: conv1 GEMM (ncu profile slot)
    k_mma<0><<<mmaBlocks, 256, SMEM>>>(x, wtPtr + 0 * NCH * NCH, wtPtr + 1 * NCH * NCH, a1, n);
    // CSR build
    k_zero<<<(n + 255) / 256, 256>>>(n);
    k_count<<<(e + 255) / 256, 256>>>(dst, e);
    k_scan1<<<NCHUNK, CHUNK>>>(n);
    k_scan2<<<1, CHUNK>>>();
    k_scan3<<<NCHUNK, CHUNK>>>(n);
    k_dinv<<<(n + 255) / 256, 256>>>(n);
    k_fill<<<(e + 255) / 256, 256>>>(src, dst, e);
    // conv1 aggregate
    k_gather<<<gatBlocks, 256>>>(b1, accPtr, n);
    // conv2
    k_mma<1><<<mmaBlocks, 256, SMEM>>>(accPtr, wtPtr + 2 * NCH * NCH, wtPtr + 3 * NCH * NCH, a2, n);
    k_gather<<<gatBlocks, 256>>>(b2, out, n);
}